// round 10
// baseline (speedup 1.0000x reference)
#include <cuda_runtime.h>
#include <cstdint>

#define B_SZ 256
#define C_SZ 3
#define H_SZ 224
#define W_SZ 224
#define P_SZ 1024
#define E_SZ 384

// Block: (96, 4). threadIdx.x indexes groups of 4 consecutive e (96*4 = 384).
// threadIdx.y indexes p within a 4-wide sub-tile; each block handles 16 p's
// (4 iterations, 2-deep pipelined) for one batch b.
// __launch_bounds__(384,4) targets 4 CTAs/SM (48 warps, 75% occ).
__global__ __launch_bounds__(384, 4) void patch_embed_kernel(
    const float* __restrict__ x,      // (B, C, H, W)
    const int*   __restrict__ curve,  // (P, 2): [:,0]=x-coord, [:,1]=y-coord
    const float* __restrict__ Wm,     // (E, C) row-major
    const float* __restrict__ bias,   // (E,)
    float* __restrict__ out)          // (B, 1, P, E)
{
    __shared__ float sW[E_SZ * C_SZ];
    __shared__ float sB[E_SZ];

    const int tid = threadIdx.y * 96 + threadIdx.x;   // 0..383
    sW[tid]        = __ldg(&Wm[tid]);
    sW[tid + 384]  = __ldg(&Wm[tid + 384]);
    sW[tid + 768]  = __ldg(&Wm[tid + 768]);
    sB[tid]        = __ldg(&bias[tid]);
    __syncthreads();

    const int e0 = threadIdx.x * 4;
    float4 w0, w1, w2, bb;
    w0.x = sW[(e0+0)*3+0]; w0.y = sW[(e0+1)*3+0]; w0.z = sW[(e0+2)*3+0]; w0.w = sW[(e0+3)*3+0];
    w1.x = sW[(e0+0)*3+1]; w1.y = sW[(e0+1)*3+1]; w1.z = sW[(e0+2)*3+1]; w1.w = sW[(e0+3)*3+1];
    w2.x = sW[(e0+0)*3+2]; w2.y = sW[(e0+1)*3+2]; w2.z = sW[(e0+2)*3+2]; w2.w = sW[(e0+3)*3+2];
    bb.x = sB[e0+0]; bb.y = sB[e0+1]; bb.z = sB[e0+2]; bb.w = sB[e0+3];

    const int b = blockIdx.y;
    const float* xb = x + (size_t)b * (C_SZ * H_SZ * W_SZ);
    float* outb = out + (size_t)b * (P_SZ * E_SZ);

    const int pbase = blockIdx.x * 16 + threadIdx.y;
    const int2* __restrict__ cv2 = (const int2*)curve;

    // 2-deep software pipeline: prefetch gathers for i+1 while storing i.
    int2 cv = __ldg(&cv2[pbase]);
    int off = cv.y * W_SZ + cv.x;
    float c0 = __ldg(xb + off);
    float c1 = __ldg(xb + H_SZ * W_SZ + off);
    float c2 = __ldg(xb + 2 * H_SZ * W_SZ + off);

    #pragma unroll
    for (int i = 0; i < 4; i++) {
        float n0 = 0.f, n1 = 0.f, n2 = 0.f;
        if (i < 3) {
            const int2 cvn = __ldg(&cv2[pbase + (i + 1) * 4]);
            const int offn = cvn.y * W_SZ + cvn.x;
            n0 = __ldg(xb + offn);
            n1 = __ldg(xb + H_SZ * W_SZ + offn);
            n2 = __ldg(xb + 2 * H_SZ * W_SZ + offn);
        }

        const int p = pbase + i * 4;
        float4 r;
        r.x = fmaf(c0, w0.x, fmaf(c1, w1.x, fmaf(c2, w2.x, bb.x)));
        r.y = fmaf(c0, w0.y, fmaf(c1, w1.y, fmaf(c2, w2.y, bb.y)));
        r.z = fmaf(c0, w0.z, fmaf(c1, w1.z, fmaf(c2, w2.z, bb.z)));
        r.w = fmaf(c0, w0.w, fmaf(c1, w1.w, fmaf(c2, w2.w, bb.w)));
        float4* dst = (float4*)(outb + (size_t)p * E_SZ) + threadIdx.x;
        __stcs(dst, r);

        c0 = n0; c1 = n1; c2 = n2;
    }
}

extern "C" void kernel_launch(void* const* d_in, const int* in_sizes, int n_in,
                              void* d_out, int out_size) {
    const float* x     = (const float*)d_in[0];
    const int*   curve = (const int*)d_in[1];
    const float* Wm    = (const float*)d_in[2];
    const float* bias  = (const float*)d_in[3];
    float* out = (float*)d_out;

    dim3 block(96, 4);
    dim3 grid(P_SZ / 16, B_SZ);   // 64 x 256 = 16384 CTAs
    patch_embed_kernel<<<grid, block>>>(x, curve, Wm, bias, out);
}

// round 12
// speedup vs baseline: 1.1170x; 1.1170x over previous
#include <cuda_runtime.h>
#include <cstdint>

#define B_SZ 256
#define C_SZ 3
#define H_SZ 224
#define W_SZ 224
#define P_SZ 1024
#define E_SZ 384

// R6 winner structure (88.3us): block (96,4), 32 p's per CTA, unroll 8,
// batched gathers (MLP~24). Single change vs R6: plain stores instead of
// __stcs — test whether evict-first policy was throttling DRAM writeback
// scheduling (H2) or 4.9TB/s is the write ceiling (H1).
__global__ __launch_bounds__(384) void patch_embed_kernel(
    const float* __restrict__ x,      // (B, C, H, W)
    const int*   __restrict__ curve,  // (P, 2): [:,0]=x-coord, [:,1]=y-coord
    const float* __restrict__ Wm,     // (E, C) row-major
    const float* __restrict__ bias,   // (E,)
    float* __restrict__ out)          // (B, 1, P, E)
{
    __shared__ float sW[E_SZ * C_SZ];
    __shared__ float sB[E_SZ];

    const int tid = threadIdx.y * 96 + threadIdx.x;   // 0..383
    sW[tid]        = __ldg(&Wm[tid]);
    sW[tid + 384]  = __ldg(&Wm[tid + 384]);
    sW[tid + 768]  = __ldg(&Wm[tid + 768]);
    sB[tid]        = __ldg(&bias[tid]);
    __syncthreads();

    const int e0 = threadIdx.x * 4;
    float4 w0, w1, w2, bb;
    w0.x = sW[(e0+0)*3+0]; w0.y = sW[(e0+1)*3+0]; w0.z = sW[(e0+2)*3+0]; w0.w = sW[(e0+3)*3+0];
    w1.x = sW[(e0+0)*3+1]; w1.y = sW[(e0+1)*3+1]; w1.z = sW[(e0+2)*3+1]; w1.w = sW[(e0+3)*3+1];
    w2.x = sW[(e0+0)*3+2]; w2.y = sW[(e0+1)*3+2]; w2.z = sW[(e0+2)*3+2]; w2.w = sW[(e0+3)*3+2];
    bb.x = sB[e0+0]; bb.y = sB[e0+1]; bb.z = sB[e0+2]; bb.w = sB[e0+3];

    const int b = blockIdx.y;
    const float* xb = x + (size_t)b * (C_SZ * H_SZ * W_SZ);
    float* outb = out + (size_t)b * (P_SZ * E_SZ);

    const int pbase = blockIdx.x * 32 + threadIdx.y;
    const int2* __restrict__ cv2 = (const int2*)curve;

    // Phase 1: batch all index loads + gathers (MLP ~24 outstanding loads).
    float g0[8], g1[8], g2[8];
    #pragma unroll
    for (int i = 0; i < 8; i++) {
        const int2 cv = __ldg(&cv2[pbase + i * 4]);
        const int off = cv.y * W_SZ + cv.x;
        g0[i] = __ldg(xb + off);
        g1[i] = __ldg(xb + H_SZ * W_SZ + off);
        g2[i] = __ldg(xb + 2 * H_SZ * W_SZ + off);
    }

    // Phase 2: FMA + plain coalesced float4 stores (L2 write-allocate,
    // lazy writeback — let LTS schedule DRAM bursts).
    #pragma unroll
    for (int i = 0; i < 8; i++) {
        const int p = pbase + i * 4;
        float4 r;
        r.x = fmaf(g0[i], w0.x, fmaf(g1[i], w1.x, fmaf(g2[i], w2.x, bb.x)));
        r.y = fmaf(g0[i], w0.y, fmaf(g1[i], w1.y, fmaf(g2[i], w2.y, bb.y)));
        r.z = fmaf(g0[i], w0.z, fmaf(g1[i], w1.z, fmaf(g2[i], w2.z, bb.z)));
        r.w = fmaf(g0[i], w0.w, fmaf(g1[i], w1.w, fmaf(g2[i], w2.w, bb.w)));
        float4* dst = (float4*)(outb + (size_t)p * E_SZ) + threadIdx.x;
        *dst = r;
    }
}

extern "C" void kernel_launch(void* const* d_in, const int* in_sizes, int n_in,
                              void* d_out, int out_size) {
    const float* x     = (const float*)d_in[0];
    const int*   curve = (const int*)d_in[1];
    const float* Wm    = (const float*)d_in[2];
    const float* bias  = (const float*)d_in[3];
    float* out = (float*)d_out;

    dim3 block(96, 4);
    dim3 grid(P_SZ / 32, B_SZ);   // 32 x 256 = 8192 CTAs
    patch_embed_kernel<<<grid, block>>>(x, curve, Wm, bias, out);
}

// round 16
// speedup vs baseline: 1.1183x; 1.0011x over previous
#include <cuda_runtime.h>
#include <cstdint>

#define B_SZ 256
#define C_SZ 3
#define H_SZ 224
#define W_SZ 224
#define P_SZ 1024
#define E_SZ 384

// R6 inner structure (best: 88.0us) with 4x prologue amortization:
// block (96,4); each CTA handles 128 p's (4 rounds of gather-8 + store-8)
// for one batch b. Grid 2048 CTAs (was 8192) — weights staged once per CTA.
__global__ __launch_bounds__(384) void patch_embed_kernel(
    const float* __restrict__ x,      // (B, C, H, W)
    const int*   __restrict__ curve,  // (P, 2): [:,0]=x-coord, [:,1]=y-coord
    const float* __restrict__ Wm,     // (E, C) row-major
    const float* __restrict__ bias,   // (E,)
    float* __restrict__ out)          // (B, 1, P, E)
{
    __shared__ float sW[E_SZ * C_SZ];
    __shared__ float sB[E_SZ];

    const int tid = threadIdx.y * 96 + threadIdx.x;   // 0..383
    sW[tid]        = __ldg(&Wm[tid]);
    sW[tid + 384]  = __ldg(&Wm[tid + 384]);
    sW[tid + 768]  = __ldg(&Wm[tid + 768]);
    sB[tid]        = __ldg(&bias[tid]);
    __syncthreads();

    const int e0 = threadIdx.x * 4;
    float4 w0, w1, w2, bb;
    w0.x = sW[(e0+0)*3+0]; w0.y = sW[(e0+1)*3+0]; w0.z = sW[(e0+2)*3+0]; w0.w = sW[(e0+3)*3+0];
    w1.x = sW[(e0+0)*3+1]; w1.y = sW[(e0+1)*3+1]; w1.z = sW[(e0+2)*3+1]; w1.w = sW[(e0+3)*3+1];
    w2.x = sW[(e0+0)*3+2]; w2.y = sW[(e0+1)*3+2]; w2.z = sW[(e0+2)*3+2]; w2.w = sW[(e0+3)*3+2];
    bb.x = sB[e0+0]; bb.y = sB[e0+1]; bb.z = sB[e0+2]; bb.w = sB[e0+3];

    const int b = blockIdx.y;
    const float* xb = x + (size_t)b * (C_SZ * H_SZ * W_SZ);
    float* outb = out + (size_t)b * (P_SZ * E_SZ);

    const int2* __restrict__ cv2 = (const int2*)curve;

    #pragma unroll 1
    for (int t = 0; t < 4; t++) {
        const int pbase = blockIdx.x * 128 + t * 32 + threadIdx.y;

        // Phase 1: batch index loads + gathers (MLP ~24 outstanding loads).
        float g0[8], g1[8], g2[8];
        #pragma unroll
        for (int i = 0; i < 8; i++) {
            const int2 cv = __ldg(&cv2[pbase + i * 4]);
            const int off = cv.y * W_SZ + cv.x;
            g0[i] = __ldg(xb + off);
            g1[i] = __ldg(xb + H_SZ * W_SZ + off);
            g2[i] = __ldg(xb + 2 * H_SZ * W_SZ + off);
        }

        // Phase 2: FMA + coalesced float4 stores.
        #pragma unroll
        for (int i = 0; i < 8; i++) {
            const int p = pbase + i * 4;
            float4 r;
            r.x = fmaf(g0[i], w0.x, fmaf(g1[i], w1.x, fmaf(g2[i], w2.x, bb.x)));
            r.y = fmaf(g0[i], w0.y, fmaf(g1[i], w1.y, fmaf(g2[i], w2.y, bb.y)));
            r.z = fmaf(g0[i], w0.z, fmaf(g1[i], w1.z, fmaf(g2[i], w2.z, bb.z)));
            r.w = fmaf(g0[i], w0.w, fmaf(g1[i], w1.w, fmaf(g2[i], w2.w, bb.w)));
            float4* dst = (float4*)(outb + (size_t)p * E_SZ) + threadIdx.x;
            *dst = r;
        }
    }
}

extern "C" void kernel_launch(void* const* d_in, const int* in_sizes, int n_in,
                              void* d_out, int out_size) {
    const float* x     = (const float*)d_in[0];
    const int*   curve = (const int*)d_in[1];
    const float* Wm    = (const float*)d_in[2];
    const float* bias  = (const float*)d_in[3];
    float* out = (float*)d_out;

    dim3 block(96, 4);
    dim3 grid(P_SZ / 128, B_SZ);   // 8 x 256 = 2048 CTAs
    patch_embed_kernel<<<grid, block>>>(x, curve, Wm, bias, out);
}